// round 16
// baseline (speedup 1.0000x reference)
#include <cuda_runtime.h>
#include <cstdint>

// FisherLayer: N=8192, D=256, K=32 — two-pass, K1 on warp-level mma.sync (bf16).
//  K1: y4raw[n,k] = sum_d a*x^2 + u*x  (a=w^2, u=2w^2b), split-bf16 GEMM via
//      mma.sync.m16n8k16 (6 split streams); gamma = softmax_k(-0.5*(y4raw+c_k)).
//  K2: Sx[k,d]=sum_n g*x, Sx2[k,d]=sum_n g*x^2 (+S0) per-block partials.
//  K3: reduce; out_mu = w*(Sx+b*S0)/N;
//      out_sigma = (w^2*(Sx2+2b*Sx+b^2*S0)-S0)/(sqrt(2)N)

#define NROWS 8192
#define DD    256
#define KK    32
#define CTAS  128
#define RPC   64
#define GRID1 64
#define ROWS1 128

typedef unsigned long long u64;
typedef unsigned int u32;

__device__ float g_G[NROWS * KK];
__device__ __align__(128) float4 g_P[128 * CTAS * 32];
__device__ float g_PS0[CTAS * KK];

__device__ __forceinline__ u64 pack2(float lo, float hi) {
    u64 r; asm("mov.b64 %0, {%1, %2};" : "=l"(r) : "f"(lo), "f"(hi)); return r;
}
__device__ __forceinline__ u64 fma2(u64 a, u64 b, u64 c) {
    u64 d; asm("fma.rn.f32x2 %0, %1, %2, %3;" : "=l"(d) : "l"(a), "l"(b), "l"(c)); return d;
}
__device__ __forceinline__ u32 bfp(float hi, float lo) {   // hi -> upper 16 bits
    u32 r; asm("cvt.rn.bf16x2.f32 %0, %1, %2;" : "=r"(r) : "f"(hi), "f"(lo)); return r;
}
__device__ __forceinline__ float blo(u32 v) { return __uint_as_float(v << 16); }
__device__ __forceinline__ float bhi(u32 v) { return __uint_as_float(v & 0xffff0000u); }

#define MMA(dd, a0, a1, a2, a3, b0, b1)                                        \
    asm volatile(                                                              \
        "mma.sync.aligned.m16n8k16.row.col.f32.bf16.bf16.f32 "                 \
        "{%0,%1,%2,%3}, {%4,%5,%6,%7}, {%8,%9}, {%0,%1,%2,%3};"                \
        : "+f"(dd[0]), "+f"(dd[1]), "+f"(dd[2]), "+f"(dd[3])                   \
        : "r"(a0), "r"(a1), "r"(a2), "r"(a3), "r"(b0), "r"(b1))

// ---------------- K1 ----------------
// dyn smem: B tables 4 variants x [32 n][264 bf16 (528B padded row)] = 67584
//           s_y 128 x 33 fp32 = 16896; s_cp 512 f32; s_c 32 f32
#define PITCHB   528
#define BVSZ     16896           // 32 * 528
#define OFF_B    0
#define OFF_Y    67584
#define OFF_CP   84480
#define OFF_C    86528
#define SMEM1    86656

__global__ void __launch_bounds__(512, 1) k1_gamma_mma(const float* __restrict__ x,
                                                       const float* __restrict__ w,
                                                       const float* __restrict__ b) {
    extern __shared__ __align__(16) char smem[];
    float* s_y  = reinterpret_cast<float*>(smem + OFF_Y);
    float* s_cp = reinterpret_cast<float*>(smem + OFF_CP);
    float* s_c  = reinterpret_cast<float*>(smem + OFF_C);

    const int tid  = threadIdx.x;
    const int wid  = tid >> 5;      // 0..15
    const int lane = tid & 31;
    const int bid  = blockIdx.x;
    const int row0 = bid * ROWS1;

    // ---- build B tables (ah/al/uh/ul) + c_k partials ----
    {
        const int n  = tid >> 4;           // 0..31 (component)
        const int k0 = (tid & 15) * 16;    // 16 d-values per thread
        const float2* wp = reinterpret_cast<const float2*>(w + (size_t)n * DD + k0);
        const float2* bp = reinterpret_cast<const float2*>(b + (size_t)n * DD + k0);
        char* Bah = smem + OFF_B + 0 * BVSZ + n * PITCHB;
        char* Bal = smem + OFF_B + 1 * BVSZ + n * PITCHB;
        char* Buh = smem + OFF_B + 2 * BVSZ + n * PITCHB;
        char* Bul = smem + OFF_B + 3 * BVSZ + n * PITCHB;
        float cp = 0.0f;
        #pragma unroll
        for (int j = 0; j < 8; j++) {
            float2 wv = wp[j], bv = bp[j];
            float a0 = wv.x * wv.x, a1 = wv.y * wv.y;
            float u0 = 2.0f * a0 * bv.x, u1 = 2.0f * a1 * bv.y;
            cp += a0 * bv.x * bv.x + a1 * bv.y * bv.y;
            u32 ah = bfp(a1, a0);
            u32 al = bfp(a1 - bhi(ah), a0 - blo(ah));
            u32 uh = bfp(u1, u0);
            u32 ul = bfp(u1 - bhi(uh), u0 - blo(uh));
            const int off = (k0 + 2 * j) * 2;
            *reinterpret_cast<u32*>(Bah + off) = ah;
            *reinterpret_cast<u32*>(Bal + off) = al;
            *reinterpret_cast<u32*>(Buh + off) = uh;
            *reinterpret_cast<u32*>(Bul + off) = ul;
        }
        s_cp[tid] = cp;
    }
    __syncthreads();
    if (tid < 32) {
        float s = 0.0f;
        #pragma unroll
        for (int j = 0; j < 16; j++) s += s_cp[tid * 16 + j];
        s_c[tid] = s;
    }

    // ---- MMA mainloop: warp = (row-tile rt 16 rows, k-half kh 16 comps) ----
    const int rt = wid & 7;            // 8 row tiles x 16 rows = 128 rows
    const int kh = wid >> 3;           // 0/1
    const int qr = lane >> 2;          // 0..7
    const int cb = (lane & 3) * 2;     // col pair base

    float d0[4] = {0.f, 0.f, 0.f, 0.f};
    float d1[4] = {0.f, 0.f, 0.f, 0.f};

    const float* xr1 = x + (size_t)(row0 + rt * 16 + qr) * DD;
    const float* xr2 = xr1 + 8 * DD;
    const char* Br0 = smem + OFF_B + (kh * 16 + qr) * PITCHB;
    const char* Br1 = Br0 + 8 * PITCHB;

    #pragma unroll
    for (int kst = 0; kst < 16; kst++) {
        const int c1 = kst * 16 + cb;
        float2 v00 = *reinterpret_cast<const float2*>(xr1 + c1);
        float2 v01 = *reinterpret_cast<const float2*>(xr1 + c1 + 8);
        float2 v10 = *reinterpret_cast<const float2*>(xr2 + c1);
        float2 v11 = *reinterpret_cast<const float2*>(xr2 + c1 + 8);

        u32 xh0 = bfp(v00.y, v00.x), xh1 = bfp(v10.y, v10.x);
        u32 xh2 = bfp(v01.y, v01.x), xh3 = bfp(v11.y, v11.x);
        u32 xl0 = bfp(v00.y - bhi(xh0), v00.x - blo(xh0));
        u32 xl1 = bfp(v10.y - bhi(xh1), v10.x - blo(xh1));
        u32 xl2 = bfp(v01.y - bhi(xh2), v01.x - blo(xh2));
        u32 xl3 = bfp(v11.y - bhi(xh3), v11.x - blo(xh3));

        float q00x = v00.x * v00.x, q00y = v00.y * v00.y;
        float q10x = v10.x * v10.x, q10y = v10.y * v10.y;
        float q01x = v01.x * v01.x, q01y = v01.y * v01.y;
        float q11x = v11.x * v11.x, q11y = v11.y * v11.y;
        u32 qh0 = bfp(q00y, q00x), qh1 = bfp(q10y, q10x);
        u32 qh2 = bfp(q01y, q01x), qh3 = bfp(q11y, q11x);
        u32 ql0 = bfp(q00y - bhi(qh0), q00x - blo(qh0));
        u32 ql1 = bfp(q10y - bhi(qh1), q10x - blo(qh1));
        u32 ql2 = bfp(q01y - bhi(qh2), q01x - blo(qh2));
        u32 ql3 = bfp(q11y - bhi(qh3), q11x - blo(qh3));

        const int ko = (kst * 16 + cb) * 2;
        {   // ntile 0
            u32 ah0 = *reinterpret_cast<const u32*>(Br0 + ko);
            u32 ah1 = *reinterpret_cast<const u32*>(Br0 + ko + 16);
            u32 al0 = *reinterpret_cast<const u32*>(Br0 + BVSZ + ko);
            u32 al1 = *reinterpret_cast<const u32*>(Br0 + BVSZ + ko + 16);
            u32 uh0 = *reinterpret_cast<const u32*>(Br0 + 2 * BVSZ + ko);
            u32 uh1 = *reinterpret_cast<const u32*>(Br0 + 2 * BVSZ + ko + 16);
            u32 ul0 = *reinterpret_cast<const u32*>(Br0 + 3 * BVSZ + ko);
            u32 ul1 = *reinterpret_cast<const u32*>(Br0 + 3 * BVSZ + ko + 16);
            MMA(d0, qh0, qh1, qh2, qh3, ah0, ah1);
            MMA(d0, ql0, ql1, ql2, ql3, ah0, ah1);
            MMA(d0, qh0, qh1, qh2, qh3, al0, al1);
            MMA(d0, xh0, xh1, xh2, xh3, uh0, uh1);
            MMA(d0, xl0, xl1, xl2, xl3, uh0, uh1);
            MMA(d0, xh0, xh1, xh2, xh3, ul0, ul1);
        }
        {   // ntile 1
            u32 ah0 = *reinterpret_cast<const u32*>(Br1 + ko);
            u32 ah1 = *reinterpret_cast<const u32*>(Br1 + ko + 16);
            u32 al0 = *reinterpret_cast<const u32*>(Br1 + BVSZ + ko);
            u32 al1 = *reinterpret_cast<const u32*>(Br1 + BVSZ + ko + 16);
            u32 uh0 = *reinterpret_cast<const u32*>(Br1 + 2 * BVSZ + ko);
            u32 uh1 = *reinterpret_cast<const u32*>(Br1 + 2 * BVSZ + ko + 16);
            u32 ul0 = *reinterpret_cast<const u32*>(Br1 + 3 * BVSZ + ko);
            u32 ul1 = *reinterpret_cast<const u32*>(Br1 + 3 * BVSZ + ko + 16);
            MMA(d1, qh0, qh1, qh2, qh3, ah0, ah1);
            MMA(d1, ql0, ql1, ql2, ql3, ah0, ah1);
            MMA(d1, qh0, qh1, qh2, qh3, al0, al1);
            MMA(d1, xh0, xh1, xh2, xh3, uh0, uh1);
            MMA(d1, xl0, xl1, xl2, xl3, uh0, uh1);
            MMA(d1, xh0, xh1, xh2, xh3, ul0, ul1);
        }
    }

    // ---- write D fragments to padded smem ----
    {
        const int lr1 = rt * 16 + qr;
        const int lr2 = lr1 + 8;
        const int c0  = kh * 16 + cb;
        s_y[lr1 * 33 + c0]     = d0[0];
        s_y[lr1 * 33 + c0 + 1] = d0[1];
        s_y[lr2 * 33 + c0]     = d0[2];
        s_y[lr2 * 33 + c0 + 1] = d0[3];
        s_y[lr1 * 33 + c0 + 8] = d1[0];
        s_y[lr1 * 33 + c0 + 9] = d1[1];
        s_y[lr2 * 33 + c0 + 8] = d1[2];
        s_y[lr2 * 33 + c0 + 9] = d1[3];
    }
    __syncthreads();

    // ---- softmax: warp wid owns rows wid*8..+8, lane = k ----
    #pragma unroll
    for (int i = 0; i < 8; i++) {
        const int row = wid * 8 + i;
        float y = -0.5f * (s_y[row * 33 + lane] + s_c[lane]);
        float m = y;
        #pragma unroll
        for (int o = 16; o; o >>= 1) m = fmaxf(m, __shfl_xor_sync(0xffffffffu, m, o));
        float e = __expf(y - m);
        float s = e;
        #pragma unroll
        for (int o = 16; o; o >>= 1) s += __shfl_xor_sync(0xffffffffu, s, o);
        g_G[(size_t)(row0 + row) * KK + lane] = e / s;
    }
}

// ---------------- K2: weighted accumulation (+S0), 512 thr, k-half split ----
__global__ void __launch_bounds__(512, 1) k2_accum(const float* __restrict__ x) {
    __shared__ __align__(16) float s_g[RPC * KK];       // 8KB
    __shared__ float s_red0[16 * 32];

    const int tid = threadIdx.x;
    const int bid = blockIdx.x;
    const int base_row = bid * RPC;

    {   // stage gamma (64 rows x 32 k = 512 float4)
        const float4* gg = reinterpret_cast<const float4*>(g_G + (size_t)base_row * KK);
        reinterpret_cast<float4*>(s_g)[tid] = gg[tid];
    }
    __syncthreads();

    {   // S0 partials
        int k0 = tid & 31, grp = tid >> 5;   // 16 groups
        float s0p = 0.0f;
        #pragma unroll
        for (int r = grp; r < RPC; r += 16) s0p += s_g[r * KK + k0];
        s_red0[grp * 32 + k0] = s0p;
    }
    __syncthreads();
    if (tid < 32) {
        float s = 0.0f;
        #pragma unroll
        for (int j = 0; j < 16; j++) s += s_red0[j * 32 + tid];
        g_PS0[bid * KK + tid] = s;
    }

    const int dB = tid & 255;
    const int kh = tid >> 8;

    u64 accx[8], accx2[8];
    #pragma unroll
    for (int p = 0; p < 8; p++) { accx[p] = 0ull; accx2[p] = 0ull; }

    const float* xb = x + (size_t)base_row * DD + dB;

    #pragma unroll 1
    for (int r0 = 0; r0 < RPC; r0 += 4) {
        float xv[4];
        #pragma unroll
        for (int i = 0; i < 4; i++) xv[i] = xb[(r0 + i) * DD];
        #pragma unroll
        for (int i = 0; i < 4; i++) {
            float v = xv[i];
            u64 px = pack2(v, v);
            float sq = v * v;
            u64 px2 = pack2(sq, sq);
            const ulonglong2* grow =
                reinterpret_cast<const ulonglong2*>(s_g + (r0 + i) * KK + kh * 16);
            #pragma unroll
            for (int q = 0; q < 4; q++) {
                ulonglong2 gg = grow[q];
                accx [2 * q]     = fma2(gg.x, px,  accx [2 * q]);
                accx2[2 * q]     = fma2(gg.x, px2, accx2[2 * q]);
                accx [2 * q + 1] = fma2(gg.y, px,  accx [2 * q + 1]);
                accx2[2 * q + 1] = fma2(gg.y, px2, accx2[2 * q + 1]);
            }
        }
    }

    ulonglong2* pg = reinterpret_cast<ulonglong2*>(g_P);
    #pragma unroll
    for (int t = 0; t < 8; t++) {
        int p = kh * 8 + t;
        int chunk = p * 8 + (dB >> 5);
        size_t idx = ((size_t)chunk * CTAS + bid) * 32 + (dB & 31);
        ulonglong2 v; v.x = accx[t]; v.y = accx2[t];
        pg[idx] = v;
    }
}

// ---------------- K3: reduce + finalize ----------------
__global__ void __launch_bounds__(256) k3_fin(const float* __restrict__ w,
                                              const float* __restrict__ b,
                                              float* __restrict__ out) {
    __shared__ __align__(16) float4 s_red4[8 * 32];
    __shared__ float s_S0v[2];

    const int tid  = threadIdx.x;
    const int wrp  = tid >> 5;
    const int lane = tid & 31;
    const int cb   = blockIdx.x;

    const float4* src = g_P + (size_t)cb * CTAS * 32;
    const int q4 = tid & 31;
    const int rg = tid >> 5;
    float4 a = make_float4(0.f, 0.f, 0.f, 0.f);
    #pragma unroll
    for (int r = rg; r < CTAS; r += 8) {
        float4 v = src[r * 32 + q4];
        a.x += v.x; a.y += v.y; a.z += v.z; a.w += v.w;
    }
    s_red4[rg * 32 + q4] = a;

    if (wrp == 1) {
        int ks = lane >> 4;
        int j  = lane & 15;
        int p  = cb >> 3;
        float s = 0.0f;
        #pragma unroll
        for (int bb = j; bb < CTAS; bb += 16) s += g_PS0[bb * KK + 2 * p + ks];
        #pragma unroll
        for (int o = 1; o < 16; o <<= 1) s += __shfl_xor_sync(0xffffffffu, s, o);
        if (j == 0) s_S0v[ks] = s;
    }
    __syncthreads();

    if (tid < 32) {
        float4 tot = make_float4(0.f, 0.f, 0.f, 0.f);
        #pragma unroll
        for (int gq = 0; gq < 8; gq++) {
            float4 v = s_red4[gq * 32 + tid];
            tot.x += v.x; tot.y += v.y; tot.z += v.z; tot.w += v.w;
        }
        const int p  = cb >> 3;
        const int d  = (cb & 7) * 32 + tid;
        const int k0 = 2 * p, k1 = 2 * p + 1;
        const float invN   = 1.0f / (float)NROWS;
        const float invNs2 = invN * 0.70710678118654752440f;

        {
            float wv = w[k0 * DD + d], bv = b[k0 * DD + d], S0 = s_S0v[0];
            float mu  = wv * (tot.x + bv * S0) * invN;
            float Ey2 = wv * wv * (tot.z + 2.0f * bv * tot.x + bv * bv * S0);
            out[k0 * DD + d]           = (Ey2 - S0) * invNs2;
            out[KK * DD + k0 * DD + d] = mu;
        }
        {
            float wv = w[k1 * DD + d], bv = b[k1 * DD + d], S0 = s_S0v[1];
            float mu  = wv * (tot.y + bv * S0) * invN;
            float Ey2 = wv * wv * (tot.w + 2.0f * bv * tot.y + bv * bv * S0);
            out[k1 * DD + d]           = (Ey2 - S0) * invNs2;
            out[KK * DD + k1 * DD + d] = mu;
        }
    }
}

extern "C" void kernel_launch(void* const* d_in, const int* in_sizes, int n_in,
                              void* d_out, int out_size) {
    const float* x = (const float*)d_in[0];
    const float* w = (const float*)d_in[1];
    const float* b = (const float*)d_in[2];
    float* out = (float*)d_out;
    (void)in_sizes; (void)n_in; (void)out_size;

    cudaFuncSetAttribute(k1_gamma_mma, cudaFuncAttributeMaxDynamicSharedMemorySize,
                         SMEM1);
    k1_gamma_mma<<<GRID1, 512, SMEM1>>>(x, w, b);
    k2_accum<<<CTAS, 512>>>(x);
    k3_fin<<<CTAS, 256>>>(w, b, out);
}

// round 17
// speedup vs baseline: 1.1705x; 1.1705x over previous
#include <cuda_runtime.h>
#include <cstdint>

// FisherLayer: N=8192, D=256, K=32 — two-pass, K1 on mma.sync (bf16 splits).
//  K1 (grid 128 = 64 row-blocks x 2 D-halves): partial y4raw[n,k] over its
//      D-half via 6-stream split-bf16 mma.sync.m16n8k16 -> g_Y[dh][n][k].
//  K2: c_k = sum_d w^2 b^2 (fp32); y4 = half0+half1; gamma = softmax;
//      Sx/Sx2 (+S0) per-block partials.
//  K3: reduce; out_mu = w*(Sx+b*S0)/N;
//      out_sigma = (w^2*(Sx2+2b*Sx+b^2*S0)-S0)/(sqrt(2)N)

#define NROWS 8192
#define DD    256
#define KK    32
#define CTAS  128
#define RPC   64
#define ROWS1 128

typedef unsigned long long u64;
typedef unsigned int u32;

__device__ float g_Y[2 * NROWS * KK];                   // y4 partials, 2MB
__device__ __align__(128) float4 g_P[128 * CTAS * 32];
__device__ float g_PS0[CTAS * KK];

__device__ __forceinline__ u64 pack2(float lo, float hi) {
    u64 r; asm("mov.b64 %0, {%1, %2};" : "=l"(r) : "f"(lo), "f"(hi)); return r;
}
__device__ __forceinline__ u64 fma2(u64 a, u64 b, u64 c) {
    u64 d; asm("fma.rn.f32x2 %0, %1, %2, %3;" : "=l"(d) : "l"(a), "l"(b), "l"(c)); return d;
}
__device__ __forceinline__ u32 bfp(float hi, float lo) {   // hi -> upper 16 bits
    u32 r; asm("cvt.rn.bf16x2.f32 %0, %1, %2;" : "=r"(r) : "f"(hi), "f"(lo)); return r;
}
__device__ __forceinline__ float blo(u32 v) { return __uint_as_float(v << 16); }
__device__ __forceinline__ float bhi(u32 v) { return __uint_as_float(v & 0xffff0000u); }

#define MMA(dd, a0, a1, a2, a3, b0, b1)                                        \
    asm volatile(                                                              \
        "mma.sync.aligned.m16n8k16.row.col.f32.bf16.bf16.f32 "                 \
        "{%0,%1,%2,%3}, {%4,%5,%6,%7}, {%8,%9}, {%0,%1,%2,%3};"                \
        : "+f"(dd[0]), "+f"(dd[1]), "+f"(dd[2]), "+f"(dd[3])                   \
        : "r"(a0), "r"(a1), "r"(a2), "r"(a3), "r"(b0), "r"(b1))

// ---------------- K1 ----------------
// dyn smem: B tables 4 x [32 n][128 bf16 (272B padded row)] = 34816
//           s_y 128 x 33 fp32 = 16896
#define PITCHB   272
#define BVSZ     8704            // 32 * 272
#define OFF_B    0
#define OFF_Y    34816
#define SMEM1    51712

__global__ void __launch_bounds__(512, 1) k1_y4_mma(const float* __restrict__ x,
                                                    const float* __restrict__ w,
                                                    const float* __restrict__ b) {
    extern __shared__ __align__(16) char smem[];
    float* s_y = reinterpret_cast<float*>(smem + OFF_Y);

    const int tid  = threadIdx.x;
    const int wid  = tid >> 5;      // 0..15
    const int lane = tid & 31;
    const int rb   = blockIdx.x >> 1;      // row block 0..63
    const int dh   = blockIdx.x & 1;       // D half
    const int row0 = rb * ROWS1;
    const int dbase = dh * 128;

    // ---- build B tables (ah/al/uh/ul) for this D-half ----
    {
        const int n  = tid >> 4;           // component 0..31
        const int k0 = (tid & 15) * 8;     // 8 local d per thread
        const float2* wp = reinterpret_cast<const float2*>(w + (size_t)n * DD + dbase + k0);
        const float2* bp = reinterpret_cast<const float2*>(b + (size_t)n * DD + dbase + k0);
        char* Bah = smem + OFF_B + 0 * BVSZ + n * PITCHB;
        char* Bal = smem + OFF_B + 1 * BVSZ + n * PITCHB;
        char* Buh = smem + OFF_B + 2 * BVSZ + n * PITCHB;
        char* Bul = smem + OFF_B + 3 * BVSZ + n * PITCHB;
        #pragma unroll
        for (int j = 0; j < 4; j++) {
            float2 wv = wp[j], bv = bp[j];
            float a0 = wv.x * wv.x, a1 = wv.y * wv.y;
            float u0 = 2.0f * a0 * bv.x, u1 = 2.0f * a1 * bv.y;
            u32 ah = bfp(a1, a0);
            u32 al = bfp(a1 - bhi(ah), a0 - blo(ah));
            u32 uh = bfp(u1, u0);
            u32 ul = bfp(u1 - bhi(uh), u0 - blo(uh));
            const int off = (k0 + 2 * j) * 2;
            *reinterpret_cast<u32*>(Bah + off) = ah;
            *reinterpret_cast<u32*>(Bal + off) = al;
            *reinterpret_cast<u32*>(Buh + off) = uh;
            *reinterpret_cast<u32*>(Bul + off) = ul;
        }
    }
    __syncthreads();

    // ---- MMA mainloop: warp = (rt 16 rows, kh 16 comps), 8 ksteps ----
    const int rt = wid & 7;
    const int kh = wid >> 3;
    const int qr = lane >> 2;
    const int cb = (lane & 3) * 2;

    float d0[4] = {0.f, 0.f, 0.f, 0.f};
    float d1[4] = {0.f, 0.f, 0.f, 0.f};

    const float* xr1 = x + (size_t)(row0 + rt * 16 + qr) * DD + dbase;
    const float* xr2 = xr1 + 8 * DD;
    const char* Br0 = smem + OFF_B + (kh * 16 + qr) * PITCHB;
    const char* Br1 = Br0 + 8 * PITCHB;

    #pragma unroll
    for (int kst = 0; kst < 8; kst++) {
        const int c1 = kst * 16 + cb;
        float2 v00 = *reinterpret_cast<const float2*>(xr1 + c1);
        float2 v01 = *reinterpret_cast<const float2*>(xr1 + c1 + 8);
        float2 v10 = *reinterpret_cast<const float2*>(xr2 + c1);
        float2 v11 = *reinterpret_cast<const float2*>(xr2 + c1 + 8);

        u32 xh0 = bfp(v00.y, v00.x), xh1 = bfp(v10.y, v10.x);
        u32 xh2 = bfp(v01.y, v01.x), xh3 = bfp(v11.y, v11.x);
        u32 xl0 = bfp(v00.y - bhi(xh0), v00.x - blo(xh0));
        u32 xl1 = bfp(v10.y - bhi(xh1), v10.x - blo(xh1));
        u32 xl2 = bfp(v01.y - bhi(xh2), v01.x - blo(xh2));
        u32 xl3 = bfp(v11.y - bhi(xh3), v11.x - blo(xh3));

        float q00x = v00.x * v00.x, q00y = v00.y * v00.y;
        float q10x = v10.x * v10.x, q10y = v10.y * v10.y;
        float q01x = v01.x * v01.x, q01y = v01.y * v01.y;
        float q11x = v11.x * v11.x, q11y = v11.y * v11.y;
        u32 qh0 = bfp(q00y, q00x), qh1 = bfp(q10y, q10x);
        u32 qh2 = bfp(q01y, q01x), qh3 = bfp(q11y, q11x);
        u32 ql0 = bfp(q00y - bhi(qh0), q00x - blo(qh0));
        u32 ql1 = bfp(q10y - bhi(qh1), q10x - blo(qh1));
        u32 ql2 = bfp(q01y - bhi(qh2), q01x - blo(qh2));
        u32 ql3 = bfp(q11y - bhi(qh3), q11x - blo(qh3));

        const int ko = (kst * 16 + cb) * 2;
        {   // ntile 0
            u32 ah0 = *reinterpret_cast<const u32*>(Br0 + ko);
            u32 ah1 = *reinterpret_cast<const u32*>(Br0 + ko + 16);
            u32 al0 = *reinterpret_cast<const u32*>(Br0 + BVSZ + ko);
            u32 al1 = *reinterpret_cast<const u32*>(Br0 + BVSZ + ko + 16);
            u32 uh0 = *reinterpret_cast<const u32*>(Br0 + 2 * BVSZ + ko);
            u32 uh1 = *reinterpret_cast<const u32*>(Br0 + 2 * BVSZ + ko + 16);
            u32 ul0 = *reinterpret_cast<const u32*>(Br0 + 3 * BVSZ + ko);
            u32 ul1 = *reinterpret_cast<const u32*>(Br0 + 3 * BVSZ + ko + 16);
            MMA(d0, qh0, qh1, qh2, qh3, ah0, ah1);
            MMA(d0, ql0, ql1, ql2, ql3, ah0, ah1);
            MMA(d0, qh0, qh1, qh2, qh3, al0, al1);
            MMA(d0, xh0, xh1, xh2, xh3, uh0, uh1);
            MMA(d0, xl0, xl1, xl2, xl3, uh0, uh1);
            MMA(d0, xh0, xh1, xh2, xh3, ul0, ul1);
        }
        {   // ntile 1
            u32 ah0 = *reinterpret_cast<const u32*>(Br1 + ko);
            u32 ah1 = *reinterpret_cast<const u32*>(Br1 + ko + 16);
            u32 al0 = *reinterpret_cast<const u32*>(Br1 + BVSZ + ko);
            u32 al1 = *reinterpret_cast<const u32*>(Br1 + BVSZ + ko + 16);
            u32 uh0 = *reinterpret_cast<const u32*>(Br1 + 2 * BVSZ + ko);
            u32 uh1 = *reinterpret_cast<const u32*>(Br1 + 2 * BVSZ + ko + 16);
            u32 ul0 = *reinterpret_cast<const u32*>(Br1 + 3 * BVSZ + ko);
            u32 ul1 = *reinterpret_cast<const u32*>(Br1 + 3 * BVSZ + ko + 16);
            MMA(d1, qh0, qh1, qh2, qh3, ah0, ah1);
            MMA(d1, ql0, ql1, ql2, ql3, ah0, ah1);
            MMA(d1, qh0, qh1, qh2, qh3, al0, al1);
            MMA(d1, xh0, xh1, xh2, xh3, uh0, uh1);
            MMA(d1, xl0, xl1, xl2, xl3, uh0, uh1);
            MMA(d1, xh0, xh1, xh2, xh3, ul0, ul1);
        }
    }

    // ---- D fragments -> padded smem ----
    {
        const int lr1 = rt * 16 + qr;
        const int lr2 = lr1 + 8;
        const int c0  = kh * 16 + cb;
        s_y[lr1 * 33 + c0]     = d0[0];
        s_y[lr1 * 33 + c0 + 1] = d0[1];
        s_y[lr2 * 33 + c0]     = d0[2];
        s_y[lr2 * 33 + c0 + 1] = d0[3];
        s_y[lr1 * 33 + c0 + 8] = d1[0];
        s_y[lr1 * 33 + c0 + 9] = d1[1];
        s_y[lr2 * 33 + c0 + 8] = d1[2];
        s_y[lr2 * 33 + c0 + 9] = d1[3];
    }
    __syncthreads();

    // ---- coalesced write to g_Y[dh][row][32] ----
    float* gy = g_Y + (size_t)dh * NROWS * KK + (size_t)row0 * KK;
    #pragma unroll
    for (int i = 0; i < 2; i++) {
        int idx = tid + i * 512;       // 0..1023
        int row = idx >> 3;
        int c4  = (idx & 7) * 4;
        float4 v;
        v.x = s_y[row * 33 + c4];
        v.y = s_y[row * 33 + c4 + 1];
        v.z = s_y[row * 33 + c4 + 2];
        v.w = s_y[row * 33 + c4 + 3];
        *reinterpret_cast<float4*>(gy + row * KK + c4) = v;
    }
}

// ---------------- K2: softmax + weighted accumulation (+S0) ----------------
__global__ void __launch_bounds__(512, 1) k2_accum(const float* __restrict__ x,
                                                   const float* __restrict__ w,
                                                   const float* __restrict__ bb) {
    __shared__ __align__(16) float s_ysum[RPC * KK];   // 8KB
    __shared__ __align__(16) float s_g[RPC * KK];      // 8KB
    __shared__ float s_cp[512];
    __shared__ float s_c[KK];
    __shared__ float s_red0[16 * 32];

    const int tid  = threadIdx.x;
    const int wid  = tid >> 5;
    const int lane = tid & 31;
    const int bid  = blockIdx.x;
    const int base_row = bid * RPC;

    // ---- c_k partials: thread (n = tid>>4, 16 d) ----
    {
        const int n  = tid >> 4;
        const int k0 = (tid & 15) * 16;
        const float2* wp = reinterpret_cast<const float2*>(w + (size_t)n * DD + k0);
        const float2* bp = reinterpret_cast<const float2*>(bb + (size_t)n * DD + k0);
        float cp = 0.0f;
        #pragma unroll
        for (int j = 0; j < 8; j++) {
            float2 wv = wp[j], bv = bp[j];
            cp += wv.x * wv.x * bv.x * bv.x + wv.y * wv.y * bv.y * bv.y;
        }
        s_cp[tid] = cp;
    }

    // ---- load + add y4 halves ----
    {
        const float4* y0 = reinterpret_cast<const float4*>(g_Y + (size_t)base_row * KK);
        const float4* y1 = reinterpret_cast<const float4*>(
            g_Y + (size_t)NROWS * KK + (size_t)base_row * KK);
        float4 a = y0[tid], c = y1[tid];
        a.x += c.x; a.y += c.y; a.z += c.z; a.w += c.w;
        reinterpret_cast<float4*>(s_ysum)[tid] = a;
    }
    __syncthreads();
    if (tid < 32) {
        float s = 0.0f;
        #pragma unroll
        for (int j = 0; j < 16; j++) s += s_cp[tid * 16 + j];
        s_c[tid] = s;
    }
    __syncthreads();

    // ---- softmax: warp wid owns rows wid*4..+4, lane = k ----
    {
        float c_reg = s_c[lane];
        float s0acc = 0.0f;
        #pragma unroll
        for (int i = 0; i < 4; i++) {
            const int row = wid * 4 + i;
            float y = -0.5f * (s_ysum[row * KK + lane] + c_reg);
            float m = y;
            #pragma unroll
            for (int o = 16; o; o >>= 1) m = fmaxf(m, __shfl_xor_sync(0xffffffffu, m, o));
            float e = __expf(y - m);
            float s = e;
            #pragma unroll
            for (int o = 16; o; o >>= 1) s += __shfl_xor_sync(0xffffffffu, s, o);
            float g = e / s;
            s0acc += g;
            s_g[row * KK + lane] = g;
        }
        s_red0[wid * 32 + lane] = s0acc;
    }
    __syncthreads();
    if (tid < 32) {
        float s = 0.0f;
        #pragma unroll
        for (int j = 0; j < 16; j++) s += s_red0[j * 32 + tid];
        g_PS0[bid * KK + tid] = s;
    }

    // ---- phase B: thread (d = tid&255, k-half kh = tid>>8) ----
    const int dB = tid & 255;
    const int kh = tid >> 8;

    u64 accx[8], accx2[8];
    #pragma unroll
    for (int p = 0; p < 8; p++) { accx[p] = 0ull; accx2[p] = 0ull; }

    const float* xb = x + (size_t)base_row * DD + dB;

    #pragma unroll 1
    for (int r0 = 0; r0 < RPC; r0 += 4) {
        float xv[4];
        #pragma unroll
        for (int i = 0; i < 4; i++) xv[i] = xb[(r0 + i) * DD];
        #pragma unroll
        for (int i = 0; i < 4; i++) {
            float v = xv[i];
            u64 px = pack2(v, v);
            float sq = v * v;
            u64 px2 = pack2(sq, sq);
            const ulonglong2* grow =
                reinterpret_cast<const ulonglong2*>(s_g + (r0 + i) * KK + kh * 16);
            #pragma unroll
            for (int q = 0; q < 4; q++) {
                ulonglong2 gg = grow[q];
                accx [2 * q]     = fma2(gg.x, px,  accx [2 * q]);
                accx2[2 * q]     = fma2(gg.x, px2, accx2[2 * q]);
                accx [2 * q + 1] = fma2(gg.y, px,  accx [2 * q + 1]);
                accx2[2 * q + 1] = fma2(gg.y, px2, accx2[2 * q + 1]);
            }
        }
    }

    ulonglong2* pg = reinterpret_cast<ulonglong2*>(g_P);
    #pragma unroll
    for (int t = 0; t < 8; t++) {
        int p = kh * 8 + t;
        int chunk = p * 8 + (dB >> 5);
        size_t idx = ((size_t)chunk * CTAS + bid) * 32 + (dB & 31);
        ulonglong2 v; v.x = accx[t]; v.y = accx2[t];
        pg[idx] = v;
    }
}

// ---------------- K3: reduce + finalize ----------------
__global__ void __launch_bounds__(256) k3_fin(const float* __restrict__ w,
                                              const float* __restrict__ b,
                                              float* __restrict__ out) {
    __shared__ __align__(16) float4 s_red4[8 * 32];
    __shared__ float s_S0v[2];

    const int tid  = threadIdx.x;
    const int wrp  = tid >> 5;
    const int lane = tid & 31;
    const int cb   = blockIdx.x;

    const float4* src = g_P + (size_t)cb * CTAS * 32;
    const int q4 = tid & 31;
    const int rg = tid >> 5;
    float4 a = make_float4(0.f, 0.f, 0.f, 0.f);
    #pragma unroll
    for (int r = rg; r < CTAS; r += 8) {
        float4 v = src[r * 32 + q4];
        a.x += v.x; a.y += v.y; a.z += v.z; a.w += v.w;
    }
    s_red4[rg * 32 + q4] = a;

    if (wrp == 1) {
        int ks = lane >> 4;
        int j  = lane & 15;
        int p  = cb >> 3;
        float s = 0.0f;
        #pragma unroll
        for (int bbk = j; bbk < CTAS; bbk += 16) s += g_PS0[bbk * KK + 2 * p + ks];
        #pragma unroll
        for (int o = 1; o < 16; o <<= 1) s += __shfl_xor_sync(0xffffffffu, s, o);
        if (j == 0) s_S0v[ks] = s;
    }
    __syncthreads();

    if (tid < 32) {
        float4 tot = make_float4(0.f, 0.f, 0.f, 0.f);
        #pragma unroll
        for (int gq = 0; gq < 8; gq++) {
            float4 v = s_red4[gq * 32 + tid];
            tot.x += v.x; tot.y += v.y; tot.z += v.z; tot.w += v.w;
        }
        const int p  = cb >> 3;
        const int d  = (cb & 7) * 32 + tid;
        const int k0 = 2 * p, k1 = 2 * p + 1;
        const float invN   = 1.0f / (float)NROWS;
        const float invNs2 = invN * 0.70710678118654752440f;

        {
            float wv = w[k0 * DD + d], bv = b[k0 * DD + d], S0 = s_S0v[0];
            float mu  = wv * (tot.x + bv * S0) * invN;
            float Ey2 = wv * wv * (tot.z + 2.0f * bv * tot.x + bv * bv * S0);
            out[k0 * DD + d]           = (Ey2 - S0) * invNs2;
            out[KK * DD + k0 * DD + d] = mu;
        }
        {
            float wv = w[k1 * DD + d], bv = b[k1 * DD + d], S0 = s_S0v[1];
            float mu  = wv * (tot.y + bv * S0) * invN;
            float Ey2 = wv * wv * (tot.w + 2.0f * bv * tot.y + bv * bv * S0);
            out[k1 * DD + d]           = (Ey2 - S0) * invNs2;
            out[KK * DD + k1 * DD + d] = mu;
        }
    }
}

extern "C" void kernel_launch(void* const* d_in, const int* in_sizes, int n_in,
                              void* d_out, int out_size) {
    const float* x = (const float*)d_in[0];
    const float* w = (const float*)d_in[1];
    const float* b = (const float*)d_in[2];
    float* out = (float*)d_out;
    (void)in_sizes; (void)n_in; (void)out_size;

    cudaFuncSetAttribute(k1_y4_mma, cudaFuncAttributeMaxDynamicSharedMemorySize,
                         SMEM1);
    k1_y4_mma<<<CTAS, 512, SMEM1>>>(x, w, b);
    k2_accum<<<CTAS, 512>>>(x, w, b);
    k3_fin<<<CTAS, 256>>>(w, b, out);
}